// round 14
// baseline (speedup 1.0000x reference)
#include <cuda_runtime.h>
#include <cuda_bf16.h>
#include <cstdint>

#define LAYERS 2
#define DM 512
#define EPSLN 1e-5f
#define NT 256

// ---- byte offsets ----
// attention phase:
#define BY_SXP   32768u   /* bf16 patches [32][320] (h-stride 20) */
#define BY_STMP  65536u   /* f32 [32][64] */
#define BY_QB    73728u   /* bf16 [32][72] */
#define BY_KB    78336u
#define BY_VB    82944u   /* bf16 [64][72] */
#define BY_SOF   92160u   /* f32 so [32][65] */
#define BY_SPW   100480u  /* f32 qkv pw weights [32][32] */
// FFN phase:
#define BY_XP    32768u   /* xp_bf [256][40] */
#define BY_F1W   53248u   /* f1w_bf [128][40] */
#define BY_FPWW  32768u   /* fpw_bf [128][136] (after f1) */
#define BY_TA    67584u   /* t1 / t3 [256][136] */
#define BY_TB    137216u  /* t2 [256][136]; lin ping-pong bufs during attn */
#define BY_WTB0  137216u  /* [512][24] bf16 = 24576B */
#define BY_WTB1  161792u
#define BY_F2W   206848u
#define BY_SB1   215552u
#define BY_SBPW  216064u
#define BY_SB2   216576u
#define BY_FDW   216704u
#define BY_SO16B 222848u  /* so16_bf [16][264] */
#define SMEM_BYTES 231296

#define MMA_BF16(c0,c1,c2,c3,a0,a1,a2,a3,b0,b1) \
    asm volatile("mma.sync.aligned.m16n8k16.row.col.f32.bf16.bf16.f32 " \
        "{%0,%1,%2,%3}, {%4,%5,%6,%7}, {%8,%9}, {%0,%1,%2,%3};" \
        : "+f"(c0), "+f"(c1), "+f"(c2), "+f"(c3) \
        : "r"(a0), "r"(a1), "r"(a2), "r"(a3), "r"(b0), "r"(b1))

__device__ __forceinline__ uint32_t packbf(float lo, float hi) {
    uint32_t r;
    asm("cvt.rn.bf16x2.f32 %0, %1, %2;" : "=r"(r) : "f"(hi), "f"(lo));
    return r;
}

#define LDA4(A, buf, S, row, k, g, tg)                                          \
    do {                                                                        \
        (A)[0] = *(const uint32_t*)((buf) + ((row)+(g))*(S) + (k) + (tg)*2);    \
        (A)[1] = *(const uint32_t*)((buf) + ((row)+(g)+8)*(S) + (k) + (tg)*2);  \
        (A)[2] = *(const uint32_t*)((buf) + ((row)+(g))*(S) + (k) + 8 + (tg)*2);\
        (A)[3] = *(const uint32_t*)((buf) + ((row)+(g)+8)*(S) + (k) + 8 + (tg)*2);\
    } while (0)

struct Params {
    const float *x;
    const float *ln1_g, *ln1_b, *ln2_g, *ln2_b;
    const float *qkv_dw, *qkv_bng, *qkv_bnb, *qkv_bnm, *qkv_bnv, *qkv_pw;
    const float *position, *c1d_w, *c1d_b, *lin_w, *lin_b;
    const float *f1_w, *f1_b, *fdw_w, *fdw_b;
    const float *f_bng, *f_bnb, *f_bnm, *f_bnv;
    const float *fpw_w, *fpw_b, *f2_w, *f2_b;
    float *out;
};

__device__ __forceinline__ float warp_sum(float v) {
#pragma unroll
    for (int o = 16; o; o >>= 1) v += __shfl_xor_sync(0xffffffffu, v, o);
    return v;
}

extern __shared__ float sm[];

__global__ void __launch_bounds__(NT, 1) encoder_kernel(Params p) {
    const int b = blockIdx.x;
    const int tid = threadIdx.x;
    const int lane = tid & 31;
    const int wid = tid >> 5;
    const int g = lane >> 2, tg = lane & 3;
    char* smc = (char*)sm;
    float* sx = sm;

    // ---- load x (16x512) ----
    {
        const float4* xg = (const float4*)(p.x + (size_t)b * 8192);
        float4* sx4 = (float4*)sx;
#pragma unroll
        for (int it = 0; it < 8; it++) sx4[tid + NT * it] = xg[tid + NT * it];
    }
    __syncthreads();

    for (int l = 0; l < LAYERS; l++) {
        __nv_bfloat16* sxpb = (__nv_bfloat16*)(smc + BY_SXP);  // [c][h*20+w]
        float* stmp = (float*)(smc + BY_STMP);
        __nv_bfloat16* qb = (__nv_bfloat16*)(smc + BY_QB);
        __nv_bfloat16* kb = (__nv_bfloat16*)(smc + BY_KB);
        __nv_bfloat16* vb = (__nv_bfloat16*)(smc + BY_VB);
        float* so   = (float*)(smc + BY_SOF);
        float* spw  = (float*)(smc + BY_SPW);

        // ---- LN1 -> bf16 patches [c][h*20+w] ----
        {
            const float* gg = p.ln1_g + l * DM; const float* bb = p.ln1_b + l * DM;
#pragma unroll
            for (int r = 0; r < 2; r++) {
                int h = wid + 8 * r;
                float s = 0.f, ss = 0.f;
#pragma unroll
                for (int i = 0; i < 16; i++) {
                    float v = sx[h * 512 + lane + 32 * i];
                    s += v; ss += v * v;
                }
                s = warp_sum(s); ss = warp_sum(ss);
                float mean = s * (1.f / 512.f);
                float rs = rsqrtf(ss * (1.f / 512.f) - mean * mean + EPSLN);
#pragma unroll
                for (int i = 0; i < 16; i++) {
                    int j = lane + 32 * i;
                    float v = (sx[h * 512 + j] - mean) * rs * gg[j] + bb[j];
                    sxpb[(j >> 4) * 320 + h * 20 + (j & 15)] = __float2bfloat16(v);
                }
            }
        }
        __syncthreads();

        // ---- q/k/v: dw3x3 s2 + BN + pw (bf16 dwconv, paired outputs) ----
        for (int i = 0; i < 3; i++) {
            const float* dw  = p.qkv_dw  + (size_t)((l * 3 + i) * 32) * 9;
            const float* bng = p.qkv_bng + (l * 3 + i) * 32;
            const float* bnb = p.qkv_bnb + (l * 3 + i) * 32;
            const float* bnm = p.qkv_bnm + (l * 3 + i) * 32;
            const float* bnv = p.qkv_bnv + (l * 3 + i) * 32;
            {
                const float4* pwg = (const float4*)(p.qkv_pw + (size_t)((l * 3 + i) * 32) * 32);
                *(float4*)(spw + tid * 4) = pwg[tid];
            }
#pragma unroll
            for (int it = 0; it < 4; it++) {
                int u = tid + NT * it;          // 0..1023
                int c = u >> 5, r = u & 31;
                int oh = r >> 2, owp = r & 3;
                const float* wp = dw + c * 9;
                float k0 = wp[0], k1 = wp[1], k2 = wp[2];
                float k3 = wp[3], k4 = wp[4], k5 = wp[5];
                float k6 = wp[6], k7 = wp[7], k8 = wp[8];
                const __nv_bfloat16* cb = sxpb + c * 320;
                int wq = owp * 4;
                float o0 = 0.f, o1 = 0.f;
#pragma unroll
                for (int kh = 0; kh < 3; kh++) {
                    int ih = 2 * oh - 1 + kh;
                    float f1, f2, f3, f4, f5;
                    if (ih >= 0) {
                        const __nv_bfloat16* rp = cb + ih * 20 + wq;
                        float2 m = __bfloat1622float2(*(const __nv_bfloat162*)(rp));
                        float2 hi = __bfloat1622float2(*(const __nv_bfloat162*)(rp + 2));
                        f2 = m.x; f3 = m.y; f4 = hi.x; f5 = hi.y;
                        f1 = (owp > 0)
                            ? __bfloat1622float2(*(const __nv_bfloat162*)(rp - 2)).y : 0.f;
                    } else { f1 = f2 = f3 = f4 = f5 = 0.f; }
                    float kk0 = (kh == 0) ? k0 : (kh == 1 ? k3 : k6);
                    float kk1 = (kh == 0) ? k1 : (kh == 1 ? k4 : k7);
                    float kk2 = (kh == 0) ? k2 : (kh == 1 ? k5 : k8);
                    o0 += f1 * kk0 + f2 * kk1 + f3 * kk2;
                    o1 += f3 * kk0 + f4 * kk1 + f5 * kk2;
                }
                float sc = bng[c] * rsqrtf(bnv[c] + EPSLN);
                float sh = bnb[c] - bnm[c] * sc;
                *(float2*)(stmp + c * 64 + oh * 8 + owp * 2) =
                    make_float2(o0 * sc + sh, o1 * sc + sh);
            }
            __syncthreads();
            {   // pw 32->32, bf16 out
                int pos = tid & 63, dblk = tid >> 6;
                float acc[8];
#pragma unroll
                for (int j = 0; j < 8; j++) acc[j] = 0.f;
#pragma unroll
                for (int c = 0; c < 32; c += 4) {
                    float s0 = stmp[(c + 0) * 64 + pos];
                    float s1 = stmp[(c + 1) * 64 + pos];
                    float s2 = stmp[(c + 2) * 64 + pos];
                    float s3 = stmp[(c + 3) * 64 + pos];
#pragma unroll
                    for (int j = 0; j < 8; j++) {
                        float4 w = *(const float4*)(spw + (dblk * 8 + j) * 32 + c);
                        acc[j] += s0 * w.x + s1 * w.y + s2 * w.z + s3 * w.w;
                    }
                }
                if (i < 2) {
                    __nv_bfloat16* dst = (i == 0) ? qb : kb;
#pragma unroll
                    for (int j = 0; j < 8; j++)
                        dst[(dblk * 8 + j) * 72 + pos] = __float2bfloat16(acc[j]);
                } else {   // v transposed: [pos][feature]
#pragma unroll
                    for (int jj = 0; jj < 4; jj++)
                        *(uint32_t*)(vb + pos * 72 + dblk * 8 + jj * 2) =
                            packbf(acc[2 * jj], acc[2 * jj + 1]);
                }
            }
            __syncthreads();
        }

        // ---- attention via mma (warps 0,1) ----
        if (wid < 2) {
            const float* posw = p.position + l * 1024;
            int m0 = wid * 16;
            uint32_t Aq[4][4];
#pragma unroll
            for (int kt = 0; kt < 4; kt++) LDA4(Aq[kt], qb, 72, m0, kt * 16, g, tg);
            float c[4][4];
#pragma unroll
            for (int nt = 0; nt < 4; nt++) {
                c[nt][0] = c[nt][1] = c[nt][2] = c[nt][3] = 0.f;
#pragma unroll
                for (int kt = 0; kt < 4; kt++) {
                    uint32_t b0 = *(const uint32_t*)(kb + (nt * 8 + g) * 72 + kt * 16 + tg * 2);
                    uint32_t b1 = *(const uint32_t*)(kb + (nt * 8 + g) * 72 + kt * 16 + 8 + tg * 2);
                    MMA_BF16(c[nt][0], c[nt][1], c[nt][2], c[nt][3],
                             Aq[kt][0], Aq[kt][1], Aq[kt][2], Aq[kt][3], b0, b1);
                }
            }
#pragma unroll
            for (int nt = 0; nt < 4; nt++) {
                int col = nt * 8 + tg * 2;
                c[nt][0] = c[nt][0] * 0.125f + posw[(m0 + g) * 32 + col];
                c[nt][1] = c[nt][1] * 0.125f + posw[(m0 + g) * 32 + col + 1];
                c[nt][2] = c[nt][2] * 0.125f + posw[(m0 + g + 8) * 32 + col];
                c[nt][3] = c[nt][3] * 0.125f + posw[(m0 + g + 8) * 32 + col + 1];
            }
            float mx0 = -1e30f, mx1 = -1e30f;
#pragma unroll
            for (int nt = 0; nt < 4; nt++) {
                mx0 = fmaxf(mx0, fmaxf(c[nt][0], c[nt][1]));
                mx1 = fmaxf(mx1, fmaxf(c[nt][2], c[nt][3]));
            }
#pragma unroll
            for (int o = 1; o <= 2; o <<= 1) {
                mx0 = fmaxf(mx0, __shfl_xor_sync(0xffffffffu, mx0, o));
                mx1 = fmaxf(mx1, __shfl_xor_sync(0xffffffffu, mx1, o));
            }
            float sm0 = 0.f, sm1 = 0.f;
#pragma unroll
            for (int nt = 0; nt < 4; nt++) {
                c[nt][0] = __expf(c[nt][0] - mx0); sm0 += c[nt][0];
                c[nt][1] = __expf(c[nt][1] - mx0); sm0 += c[nt][1];
                c[nt][2] = __expf(c[nt][2] - mx1); sm1 += c[nt][2];
                c[nt][3] = __expf(c[nt][3] - mx1); sm1 += c[nt][3];
            }
#pragma unroll
            for (int o = 1; o <= 2; o <<= 1) {
                sm0 += __shfl_xor_sync(0xffffffffu, sm0, o);
                sm1 += __shfl_xor_sync(0xffffffffu, sm1, o);
            }
            float i0 = 1.f / sm0, i1 = 1.f / sm1;
#pragma unroll
            for (int nt = 0; nt < 4; nt++) {
                c[nt][0] *= i0; c[nt][1] *= i0; c[nt][2] *= i1; c[nt][3] *= i1;
            }
            uint32_t Ap[2][4];
#pragma unroll
            for (int kt2 = 0; kt2 < 2; kt2++) {
                Ap[kt2][0] = packbf(c[2 * kt2][0], c[2 * kt2][1]);
                Ap[kt2][1] = packbf(c[2 * kt2][2], c[2 * kt2][3]);
                Ap[kt2][2] = packbf(c[2 * kt2 + 1][0], c[2 * kt2 + 1][1]);
                Ap[kt2][3] = packbf(c[2 * kt2 + 1][2], c[2 * kt2 + 1][3]);
            }
#pragma unroll
            for (int nt = 0; nt < 8; nt++) {
                float o0 = 0.f, o1 = 0.f, o2 = 0.f, o3 = 0.f;
#pragma unroll
                for (int kt2 = 0; kt2 < 2; kt2++) {
                    uint32_t b0 = *(const uint32_t*)(vb + (nt * 8 + g) * 72 + kt2 * 16 + tg * 2);
                    uint32_t b1 = *(const uint32_t*)(vb + (nt * 8 + g) * 72 + kt2 * 16 + 8 + tg * 2);
                    MMA_BF16(o0, o1, o2, o3, Ap[kt2][0], Ap[kt2][1], Ap[kt2][2], Ap[kt2][3], b0, b1);
                }
                int colE = nt * 8 + tg * 2;
                so[(m0 + g) * 65 + colE]     = o0;
                so[(m0 + g) * 65 + colE + 1] = o1;
                so[(m0 + g + 8) * 65 + colE]     = o2;
                so[(m0 + g + 8) * 65 + colE + 1] = o3;
            }
        }
        __syncthreads();

        // ---- c1d 8->16 -> bf16 [16][264] ----
        {
            __nv_bfloat16* so16b = (__nv_bfloat16*)(smc + BY_SO16B);
            int d = tid >> 3, p2 = tid & 7;
            float vals[8];
#pragma unroll
            for (int c = 0; c < 8; c++) vals[c] = so[d * 65 + c * 8 + p2];
            const float* w = p.c1d_w + l * 128;
            const float* bb = p.c1d_b + l * 16;
#pragma unroll
            for (int o = 0; o < 16; o++) {
                float acc = bb[o];
#pragma unroll
                for (int c = 0; c < 8; c++) acc += w[o * 8 + c] * vals[c];
                so16b[o * 264 + tid] = __float2bfloat16(acc);
            }
        }
        __syncthreads();

        // ---- lin via mma with ping-pong k-chunks of 16 ----
        {
            const float* lw = p.lin_w + (size_t)l * 131072;
            __nv_bfloat16* wtb[2] = { (__nv_bfloat16*)(smc + BY_WTB0),
                                      (__nv_bfloat16*)(smc + BY_WTB1) };
            const __nv_bfloat16* so16b = (const __nv_bfloat16*)(smc + BY_SO16B);
            float acc[8][4];
#pragma unroll
            for (int n = 0; n < 8; n++)
#pragma unroll
                for (int q = 0; q < 4; q++) acc[n][q] = 0.f;

            // stage chunk 0
#pragma unroll
            for (int it = 0; it < 8; it++) {
                int e4 = tid + NT * it;        // 0..2047
                int o = e4 >> 2, k4 = (e4 & 3) * 4;
                float4 v = *(const float4*)(lw + o * 256 + k4);
                *(uint2*)(wtb[0] + o * 24 + k4) =
                    make_uint2(packbf(v.x, v.y), packbf(v.z, v.w));
            }
            __syncthreads();
            for (int ch = 0; ch < 16; ch++) {
                if (ch < 15) {
                    int d1 = (ch + 1) * 16;
                    __nv_bfloat16* wb = wtb[(ch + 1) & 1];
#pragma unroll
                    for (int it = 0; it < 8; it++) {
                        int e4 = tid + NT * it;
                        int o = e4 >> 2, k4 = (e4 & 3) * 4;
                        float4 v = *(const float4*)(lw + o * 256 + d1 + k4);
                        *(uint2*)(wb + o * 24 + k4) =
                            make_uint2(packbf(v.x, v.y), packbf(v.z, v.w));
                    }
                }
                const __nv_bfloat16* wb = wtb[ch & 1];
                uint32_t A[4];
                LDA4(A, so16b, 264, 0, ch * 16, g, tg);
#pragma unroll
                for (int n = 0; n < 8; n++) {
                    int n0 = (wid * 8 + n) * 8;
                    uint32_t b0 = *(const uint32_t*)(wb + (n0 + g) * 24 + tg * 2);
                    uint32_t b1 = *(const uint32_t*)(wb + (n0 + g) * 24 + 8 + tg * 2);
                    MMA_BF16(acc[n][0], acc[n][1], acc[n][2], acc[n][3],
                             A[0], A[1], A[2], A[3], b0, b1);
                }
                __syncthreads();
            }
            const float* lb = p.lin_b + l * 512;
#pragma unroll
            for (int n = 0; n < 8; n++) {
                int o = (wid * 8 + n) * 8 + tg * 2;
                sx[g * 512 + o]           += acc[n][0] + lb[o];
                sx[g * 512 + o + 1]       += acc[n][1] + lb[o + 1];
                sx[(g + 8) * 512 + o]     += acc[n][2] + lb[o];
                sx[(g + 8) * 512 + o + 1] += acc[n][3] + lb[o + 1];
            }
        }
        __syncthreads();

        // ================= conv-FFN sublayer =================
        __nv_bfloat16* xpb  = (__nv_bfloat16*)(smc + BY_XP);
        __nv_bfloat16* f1wb = (__nv_bfloat16*)(smc + BY_F1W);
        __nv_bfloat16* t1   = (__nv_bfloat16*)(smc + BY_TA);
        __nv_bfloat16* t2   = (__nv_bfloat16*)(smc + BY_TB);
        __nv_bfloat16* fpwb = (__nv_bfloat16*)(smc + BY_FPWW);
        __nv_bfloat16* t3   = (__nv_bfloat16*)(smc + BY_TA);
        __nv_bfloat16* f2wb = (__nv_bfloat16*)(smc + BY_F2W);
        float* sb1  = (float*)(smc + BY_SB1);
        float* sbpw = (float*)(smc + BY_SBPW);
        float* sb2  = (float*)(smc + BY_SB2);
        float* sfdw = (float*)(smc + BY_FDW);

        {   // LN2 -> xp_bf [pos][40]
            const float* gg = p.ln2_g + l * DM; const float* bb = p.ln2_b + l * DM;
#pragma unroll
            for (int r = 0; r < 2; r++) {
                int h = wid + 8 * r;
                float s = 0.f, ss = 0.f;
#pragma unroll
                for (int i = 0; i < 16; i++) {
                    float v = sx[h * 512 + lane + 32 * i];
                    s += v; ss += v * v;
                }
                s = warp_sum(s); ss = warp_sum(ss);
                float mean = s * (1.f / 512.f);
                float rs = rsqrtf(ss * (1.f / 512.f) - mean * mean + EPSLN);
#pragma unroll
                for (int i = 0; i < 16; i++) {
                    int j = lane + 32 * i;
                    float v = (sx[h * 512 + j] - mean) * rs * gg[j] + bb[j];
                    int d = j >> 4, pp = h * 16 + (j & 15);
                    xpb[pp * 40 + d] = __float2bfloat16(v);
                }
            }
        }
        {   // stage f1w, f2w, biases, folded dw
            const float* w1 = p.f1_w + l * 4096;
#pragma unroll
            for (int it = 0; it < 4; it++) {
                int e4 = tid + NT * it;
                int n = e4 >> 3, k4 = (e4 & 7) * 4;
                float4 v = *(const float4*)(w1 + n * 32 + k4);
                *(uint2*)(f1wb + n * 40 + k4) =
                    make_uint2(packbf(v.x, v.y), packbf(v.z, v.w));
            }
            const float* w2 = p.f2_w + l * 4096;
#pragma unroll
            for (int it = 0; it < 4; it++) {
                int e4 = tid + NT * it;
                int i2 = e4 >> 5, o4 = (e4 & 31) * 4;
                float4 v = *(const float4*)(w2 + i2 * 128 + o4);
                *(uint2*)(f2wb + i2 * 136 + o4) =
                    make_uint2(packbf(v.x, v.y), packbf(v.z, v.w));
            }
            if (tid < 128) {
                sb1[tid]  = p.f1_b[l * 128 + tid];
                sbpw[tid] = p.fpw_b[l * 128 + tid];
                float* fw = sfdw + tid * 12;
                const float* dwp = p.fdw_w + l * 1152 + tid * 9;
#pragma unroll
                for (int k = 0; k < 9; k++) fw[k] = dwp[k];
                float sc = p.f_bng[l * 128 + tid] * rsqrtf(p.f_bnv[l * 128 + tid] + EPSLN);
                fw[9] = sc;
                fw[10] = (p.fdw_b[l * 128 + tid] - p.f_bnm[l * 128 + tid]) * sc
                         + p.f_bnb[l * 128 + tid];
            }
            if (tid < 32) sb2[tid] = p.f2_b[l * 32 + tid];
        }
        __syncthreads();

        // ---- f1: [256,128] = xp @ f1w^T, +bias, ReLU -> t1 ----
#pragma unroll
        for (int mi = 0; mi < 2; mi++) {
            int row = (wid * 2 + mi) * 16;
            uint32_t A[2][4];
#pragma unroll
            for (int ks = 0; ks < 2; ks++) LDA4(A[ks], xpb, 40, row, ks * 16, g, tg);
#pragma unroll
            for (int n = 0; n < 16; n++) {
                int n0 = n * 8;
                float bias0 = sb1[n0 + tg * 2], bias1 = sb1[n0 + tg * 2 + 1];
                float c0 = bias0, c1 = bias1, c2 = bias0, c3 = bias1;
#pragma unroll
                for (int ks = 0; ks < 2; ks++) {
                    int k = ks * 16;
                    uint32_t b0 = *(const uint32_t*)(f1wb + (n0 + g) * 40 + k + tg * 2);
                    uint32_t b1 = *(const uint32_t*)(f1wb + (n0 + g) * 40 + k + 8 + tg * 2);
                    MMA_BF16(c0, c1, c2, c3, A[ks][0], A[ks][1], A[ks][2], A[ks][3], b0, b1);
                }
                *(uint32_t*)(t1 + (row + g) * 136 + n0 + tg * 2) =
                    packbf(fmaxf(c0, 0.f), fmaxf(c1, 0.f));
                *(uint32_t*)(t1 + (row + g + 8) * 136 + n0 + tg * 2) =
                    packbf(fmaxf(c2, 0.f), fmaxf(c3, 0.f));
            }
        }
        __syncthreads();

        // ---- dw3x3 s1 + BN (rolling window, channel pairs) -> t2 ----
        {
            int cp = tid & 63, wq = tid >> 6;
            int w0 = wq * 4, c0 = cp * 2;
            const float* fwa = sfdw + c0 * 12;
            const float* fwb = sfdw + (c0 + 1) * 12;
            float2 kc[9];
#pragma unroll
            for (int t = 0; t < 9; t++) kc[t] = make_float2(fwa[t], fwb[t]);
            float2 scl = make_float2(fwa[9], fwb[9]);
            float2 shf = make_float2(fwa[10], fwb[10]);

            float2 rA[6], rB[6], rC[6];
#pragma unroll
            for (int i = 0; i < 6; i++) {
                rA[i] = make_float2(0.f, 0.f);
                int iw = w0 - 1 + i;
                rB[i] = ((unsigned)iw < 16u)
                    ? __bfloat1622float2(*(const __nv_bfloat162*)(t1 + iw * 136 + c0))
                    : make_float2(0.f, 0.f);
            }
#pragma unroll
            for (int h = 0; h < 16; h++) {
                if (h < 15) {
#pragma unroll
                    for (int i = 0; i < 6; i++) {
                        int iw = w0 - 1 + i;
                        rC[i] = ((unsigned)iw < 16u)
                            ? __bfloat1622float2(*(const __nv_bfloat162*)(t1 + ((h + 1) * 16 + iw) * 136 + c0))
                            : make_float2(0.f, 0.f);
                    }
                } else {
#pragma unroll
                    for (int i = 0; i < 6; i++) rC[i] = make_float2(0.f, 0.f);
                }
#pragma unroll
                for (int j = 0; j < 4; j++) {
                    float ax = rA[j].x * kc[0].x + rA[j+1].x * kc[1].x + rA[j+2].x * kc[2].x
                             + rB[j].x * kc[3].x + rB[j+1].x * kc[4].x + rB[j+2].x * kc[5].x
                             + rC[j].x * kc[6].x + rC[j+1].x * kc[7].x + rC[j+2].x * kc[8].x;
                    float ay = rA[j].y * kc[0].y + rA[j+1].y * kc[1].y + rA[j+2].y * kc[2].y
                             + rB[j].y * kc[3].y + rB[j+1].y * kc[4].y + rB[j+2].y * kc[5].y
                             + rC[j].y * kc[6].y + rC[j+1].y * kc[7].y + rC[j+2].y * kc[8].y;
                    *(uint32_t*)(t2 + (h * 16 + w0 + j) * 136 + c0) =
                        packbf(ax * scl.x + shf.x, ay * scl.y + shf.y);
                }
#pragma unroll
                for (int i = 0; i < 6; i++) { rA[i] = rB[i]; rB[i] = rC[i]; }
            }
            // stage fpw weights (overlays dead xp/f1w)
            const float* wpw = p.fpw_w + (size_t)l * 16384;
#pragma unroll
            for (int it = 0; it < 16; it++) {
                int e4 = tid + NT * it;
                int o = e4 >> 5, c4 = (e4 & 31) * 4;
                float4 v = *(const float4*)(wpw + o * 128 + c4);
                *(uint2*)(fpwb + o * 136 + c4) =
                    make_uint2(packbf(v.x, v.y), packbf(v.z, v.w));
            }
        }
        __syncthreads();

        // ---- fpw: [256,128] = t2 @ fpw^T, +bias, ReLU -> t3 ----
#pragma unroll
        for (int mi = 0; mi < 2; mi++) {
            int row = (wid * 2 + mi) * 16;
            uint32_t A[8][4];
#pragma unroll
            for (int ks = 0; ks < 8; ks++) LDA4(A[ks], t2, 136, row, ks * 16, g, tg);
#pragma unroll
            for (int n = 0; n < 16; n++) {
                int n0 = n * 8;
                float bias0 = sbpw[n0 + tg * 2], bias1 = sbpw[n0 + tg * 2 + 1];
                float c0 = bias0, c1 = bias1, c2 = bias0, c3 = bias1;
#pragma unroll
                for (int ks = 0; ks < 8; ks++) {
                    int k = ks * 16;
                    uint32_t b0 = *(const uint32_t*)(fpwb + (n0 + g) * 136 + k + tg * 2);
                    uint32_t b1 = *(const uint32_t*)(fpwb + (n0 + g) * 136 + k + 8 + tg * 2);
                    MMA_BF16(c0, c1, c2, c3, A[ks][0], A[ks][1], A[ks][2], A[ks][3], b0, b1);
                }
                *(uint32_t*)(t3 + (row + g) * 136 + n0 + tg * 2) =
                    packbf(fmaxf(c0, 0.f), fmaxf(c1, 0.f));
                *(uint32_t*)(t3 + (row + g + 8) * 136 + n0 + tg * 2) =
                    packbf(fmaxf(c2, 0.f), fmaxf(c3, 0.f));
            }
        }
        __syncthreads();

        // ---- f2: [256,32] = t3 @ f2w^T, +bias, residual -> sx ----
#pragma unroll
        for (int mi = 0; mi < 2; mi++) {
            int row = (wid * 2 + mi) * 16;
            uint32_t A[8][4];
#pragma unroll
            for (int ks = 0; ks < 8; ks++) LDA4(A[ks], t3, 136, row, ks * 16, g, tg);
#pragma unroll
            for (int n = 0; n < 4; n++) {
                int n0 = n * 8;
                float c0 = 0.f, c1 = 0.f, c2 = 0.f, c3 = 0.f;
#pragma unroll
                for (int ks = 0; ks < 8; ks++) {
                    int k = ks * 16;
                    uint32_t b0 = *(const uint32_t*)(f2wb + (n0 + g) * 136 + k + tg * 2);
                    uint32_t b1 = *(const uint32_t*)(f2wb + (n0 + g) * 136 + k + 8 + tg * 2);
                    MMA_BF16(c0, c1, c2, c3, A[ks][0], A[ks][1], A[ks][2], A[ks][3], b0, b1);
                }
                int i = n0 + tg * 2;
                int pos = row + g, h = pos >> 4, w = pos & 15;
                sx[h * 512 + i * 16 + w]       += c0 + sb2[i];
                sx[h * 512 + (i + 1) * 16 + w] += c1 + sb2[i + 1];
                pos = row + g + 8; h = pos >> 4; w = pos & 15;
                sx[h * 512 + i * 16 + w]       += c2 + sb2[i];
                sx[h * 512 + (i + 1) * 16 + w] += c3 + sb2[i + 1];
            }
        }
        __syncthreads();
    } // layers

    // ---- write out ----
    {
        float4* og = (float4*)(p.out + (size_t)b * 8192);
        const float4* sx4 = (const float4*)sx;
#pragma unroll
        for (int it = 0; it < 8; it++) og[tid + NT * it] = sx4[tid + NT * it];
    }
}

extern "C" void kernel_launch(void* const* d_in, const int* in_sizes, int n_in,
                              void* d_out, int out_size) {
    Params p;
    p.x        = (const float*)d_in[0];
    p.ln1_g    = (const float*)d_in[1];
    p.ln1_b    = (const float*)d_in[2];
    p.ln2_g    = (const float*)d_in[3];
    p.ln2_b    = (const float*)d_in[4];
    p.qkv_dw   = (const float*)d_in[5];
    p.qkv_bng  = (const float*)d_in[6];
    p.qkv_bnb  = (const float*)d_in[7];
    p.qkv_bnm  = (const float*)d_in[8];
    p.qkv_bnv  = (const float*)d_in[9];
    p.qkv_pw   = (const float*)d_in[10];
    p.position = (const float*)d_in[11];
    p.c1d_w    = (const float*)d_in[12];
    p.c1d_b    = (const float*)d_in[13];
    p.lin_w    = (const float*)d_in[14];
    p.lin_b    = (const float*)d_in[15];
    p.f1_w     = (const float*)d_in[16];
    p.f1_b     = (const float*)d_in[17];
    p.fdw_w    = (const float*)d_in[18];
    p.fdw_b    = (const float*)d_in[19];
    p.f_bng    = (const float*)d_in[20];
    p.f_bnb    = (const float*)d_in[21];
    p.f_bnm    = (const float*)d_in[22];
    p.f_bnv    = (const float*)d_in[23];
    p.fpw_w    = (const float*)d_in[24];
    p.fpw_b    = (const float*)d_in[25];
    p.f2_w     = (const float*)d_in[26];
    p.f2_b     = (const float*)d_in[27];
    p.out      = (float*)d_out;

    int nb = in_sizes[0] / (16 * 512);   // 2048

    cudaFuncSetAttribute(encoder_kernel,
                         cudaFuncAttributeMaxDynamicSharedMemorySize, SMEM_BYTES);
    encoder_kernel<<<nb, NT, SMEM_BYTES>>>(p);
}

// round 15
// speedup vs baseline: 1.5903x; 1.5903x over previous
#include <cuda_runtime.h>
#include <cuda_bf16.h>
#include <cstdint>

#define LAYERS 2
#define DM 512
#define EPSLN 1e-5f
#define NT 256

// ---- byte offsets ----
// attention phase:
#define BY_SXP   32768u   /* bf16 patches [32][320] (h-stride 20) */
#define BY_QB    73728u   /* bf16 [32][72] */
#define BY_KB    78336u
#define BY_VB    82944u   /* bf16 [64][72] */
#define BY_SOF   92160u   /* f32 so [32][65] (written after pw) */
#define BY_SPWA  92160u   /* f32 qkv pw weights 3x[32][32] (dead before so) */
#define BY_STMPA 104576u  /* f32 3x[32][64] dwconv outputs -> 129152 */
// FFN phase:
#define BY_XP    32768u   /* xp_bf [256][40] */
#define BY_F1W   53248u   /* f1w_bf [128][40] */
#define BY_FPWW  32768u   /* fpw_bf [128][136] (after f1) */
#define BY_TA    67584u   /* t1 / t3 [256][136] */
#define BY_TB    137216u  /* t2 [256][136]; lin wtb [512][72] during attn */
#define BY_F2W   206848u
#define BY_SB1   215552u
#define BY_SBPW  216064u
#define BY_SB2   216576u
#define BY_FDW   216704u
#define BY_SO16B 222848u  /* so16_bf [16][264] */
#define SMEM_BYTES 231296

#define MMA_BF16(c0,c1,c2,c3,a0,a1,a2,a3,b0,b1) \
    asm volatile("mma.sync.aligned.m16n8k16.row.col.f32.bf16.bf16.f32 " \
        "{%0,%1,%2,%3}, {%4,%5,%6,%7}, {%8,%9}, {%0,%1,%2,%3};" \
        : "+f"(c0), "+f"(c1), "+f"(c2), "+f"(c3) \
        : "r"(a0), "r"(a1), "r"(a2), "r"(a3), "r"(b0), "r"(b1))

__device__ __forceinline__ uint32_t packbf(float lo, float hi) {
    uint32_t r;
    asm("cvt.rn.bf16x2.f32 %0, %1, %2;" : "=r"(r) : "f"(hi), "f"(lo));
    return r;
}

#define LDA4(A, buf, S, row, k, g, tg)                                          \
    do {                                                                        \
        (A)[0] = *(const uint32_t*)((buf) + ((row)+(g))*(S) + (k) + (tg)*2);    \
        (A)[1] = *(const uint32_t*)((buf) + ((row)+(g)+8)*(S) + (k) + (tg)*2);  \
        (A)[2] = *(const uint32_t*)((buf) + ((row)+(g))*(S) + (k) + 8 + (tg)*2);\
        (A)[3] = *(const uint32_t*)((buf) + ((row)+(g)+8)*(S) + (k) + 8 + (tg)*2);\
    } while (0)

struct Params {
    const float *x;
    const float *ln1_g, *ln1_b, *ln2_g, *ln2_b;
    const float *qkv_dw, *qkv_bng, *qkv_bnb, *qkv_bnm, *qkv_bnv, *qkv_pw;
    const float *position, *c1d_w, *c1d_b, *lin_w, *lin_b;
    const float *f1_w, *f1_b, *fdw_w, *fdw_b;
    const float *f_bng, *f_bnb, *f_bnm, *f_bnv;
    const float *fpw_w, *fpw_b, *f2_w, *f2_b;
    float *out;
};

__device__ __forceinline__ float warp_sum(float v) {
#pragma unroll
    for (int o = 16; o; o >>= 1) v += __shfl_xor_sync(0xffffffffu, v, o);
    return v;
}

extern __shared__ float sm[];

__global__ void __launch_bounds__(NT, 1) encoder_kernel(Params p) {
    const int b = blockIdx.x;
    const int tid = threadIdx.x;
    const int lane = tid & 31;
    const int wid = tid >> 5;
    const int g = lane >> 2, tg = lane & 3;
    char* smc = (char*)sm;
    float* sx = sm;

    // ---- load x (16x512) ----
    {
        const float4* xg = (const float4*)(p.x + (size_t)b * 8192);
        float4* sx4 = (float4*)sx;
#pragma unroll
        for (int it = 0; it < 8; it++) sx4[tid + NT * it] = xg[tid + NT * it];
    }
    __syncthreads();

    for (int l = 0; l < LAYERS; l++) {
        __nv_bfloat16* sxpb = (__nv_bfloat16*)(smc + BY_SXP);  // [c][h*20+w]
        __nv_bfloat16* qb = (__nv_bfloat16*)(smc + BY_QB);
        __nv_bfloat16* kb = (__nv_bfloat16*)(smc + BY_KB);
        __nv_bfloat16* vb = (__nv_bfloat16*)(smc + BY_VB);
        float* so    = (float*)(smc + BY_SOF);
        float* spwa  = (float*)(smc + BY_SPWA);
        float* stmpa = (float*)(smc + BY_STMPA);

        // ---- LN1 -> bf16 patches [c][h*20+w] ----
        {
            const float* gg = p.ln1_g + l * DM; const float* bb = p.ln1_b + l * DM;
#pragma unroll
            for (int r = 0; r < 2; r++) {
                int h = wid + 8 * r;
                float s = 0.f, ss = 0.f;
#pragma unroll
                for (int i = 0; i < 16; i++) {
                    float v = sx[h * 512 + lane + 32 * i];
                    s += v; ss += v * v;
                }
                s = warp_sum(s); ss = warp_sum(ss);
                float mean = s * (1.f / 512.f);
                float rs = rsqrtf(ss * (1.f / 512.f) - mean * mean + EPSLN);
#pragma unroll
                for (int i = 0; i < 16; i++) {
                    int j = lane + 32 * i;
                    float v = (sx[h * 512 + j] - mean) * rs * gg[j] + bb[j];
                    sxpb[(j >> 4) * 320 + h * 20 + (j & 15)] = __float2bfloat16(v);
                }
            }
        }
        // stage all three pw weight sets (no sync needed before dwconv: disjoint data)
        {
            const float4* pwg = (const float4*)(p.qkv_pw + (size_t)l * 3072);
#pragma unroll
            for (int j2 = 0; j2 < 3; j2++)
                *(float4*)(spwa + (tid + 256 * j2) * 4) = pwg[tid + 256 * j2];
        }
        __syncthreads();

        // ---- merged q/k/v dwconv 3x3 s2 + BN (one pass, one sync) ----
#pragma unroll 4
        for (int it = 0; it < 12; it++) {
            int i = it >> 2;
            int u = tid + NT * (it & 3);    // 0..1023
            int c = u >> 5, r = u & 31;
            int oh = r >> 2, owp = r & 3;
            const float* wp = p.qkv_dw + (size_t)((l * 3 + i) * 32 + c) * 9;
            float k0 = wp[0], k1 = wp[1], k2 = wp[2];
            float k3 = wp[3], k4 = wp[4], k5 = wp[5];
            float k6 = wp[6], k7 = wp[7], k8 = wp[8];
            const __nv_bfloat16* cb = sxpb + c * 320;
            int wq = owp * 4;
            float o0 = 0.f, o1 = 0.f;
#pragma unroll
            for (int kh = 0; kh < 3; kh++) {
                int ih = 2 * oh - 1 + kh;
                float f1, f2, f3, f4, f5;
                if (ih >= 0) {
                    const __nv_bfloat16* rp = cb + ih * 20 + wq;
                    float2 m = __bfloat1622float2(*(const __nv_bfloat162*)(rp));
                    float2 hi = __bfloat1622float2(*(const __nv_bfloat162*)(rp + 2));
                    f2 = m.x; f3 = m.y; f4 = hi.x; f5 = hi.y;
                    f1 = (owp > 0)
                        ? __bfloat1622float2(*(const __nv_bfloat162*)(rp - 2)).y : 0.f;
                } else { f1 = f2 = f3 = f4 = f5 = 0.f; }
                float kk0 = (kh == 0) ? k0 : (kh == 1 ? k3 : k6);
                float kk1 = (kh == 0) ? k1 : (kh == 1 ? k4 : k7);
                float kk2 = (kh == 0) ? k2 : (kh == 1 ? k5 : k8);
                o0 += f1 * kk0 + f2 * kk1 + f3 * kk2;
                o1 += f3 * kk0 + f4 * kk1 + f5 * kk2;
            }
            int ci = (l * 3 + i) * 32 + c;
            float sc = p.qkv_bng[ci] * rsqrtf(p.qkv_bnv[ci] + EPSLN);
            float sh = p.qkv_bnb[ci] - p.qkv_bnm[ci] * sc;
            *(float2*)(stmpa + i * 2048 + c * 64 + oh * 8 + owp * 2) =
                make_float2(o0 * sc + sh, o1 * sc + sh);
        }
        __syncthreads();

        // ---- merged pointwise 32->32 for q, k, v ----
#pragma unroll
        for (int i = 0; i < 3; i++) {
            const float* stmp = stmpa + i * 2048;
            const float* spw  = spwa + i * 1024;
            int pos = tid & 63, dblk = tid >> 6;
            float acc[8];
#pragma unroll
            for (int j = 0; j < 8; j++) acc[j] = 0.f;
#pragma unroll
            for (int c = 0; c < 32; c += 4) {
                float s0 = stmp[(c + 0) * 64 + pos];
                float s1 = stmp[(c + 1) * 64 + pos];
                float s2 = stmp[(c + 2) * 64 + pos];
                float s3 = stmp[(c + 3) * 64 + pos];
#pragma unroll
                for (int j = 0; j < 8; j++) {
                    float4 w = *(const float4*)(spw + (dblk * 8 + j) * 32 + c);
                    acc[j] += s0 * w.x + s1 * w.y + s2 * w.z + s3 * w.w;
                }
            }
            if (i < 2) {
                __nv_bfloat16* dst = (i == 0) ? qb : kb;
#pragma unroll
                for (int j = 0; j < 8; j++)
                    dst[(dblk * 8 + j) * 72 + pos] = __float2bfloat16(acc[j]);
            } else {   // v transposed: [pos][feature]
#pragma unroll
                for (int jj = 0; jj < 4; jj++)
                    *(uint32_t*)(vb + pos * 72 + dblk * 8 + jj * 2) =
                        packbf(acc[2 * jj], acc[2 * jj + 1]);
            }
        }
        __syncthreads();

        // ---- attention via mma (warps 0,1) ----
        if (wid < 2) {
            const float* posw = p.position + l * 1024;
            int m0 = wid * 16;
            uint32_t Aq[4][4];
#pragma unroll
            for (int kt = 0; kt < 4; kt++) LDA4(Aq[kt], qb, 72, m0, kt * 16, g, tg);
            float c[4][4];
#pragma unroll
            for (int nt = 0; nt < 4; nt++) {
                c[nt][0] = c[nt][1] = c[nt][2] = c[nt][3] = 0.f;
#pragma unroll
                for (int kt = 0; kt < 4; kt++) {
                    uint32_t b0 = *(const uint32_t*)(kb + (nt * 8 + g) * 72 + kt * 16 + tg * 2);
                    uint32_t b1 = *(const uint32_t*)(kb + (nt * 8 + g) * 72 + kt * 16 + 8 + tg * 2);
                    MMA_BF16(c[nt][0], c[nt][1], c[nt][2], c[nt][3],
                             Aq[kt][0], Aq[kt][1], Aq[kt][2], Aq[kt][3], b0, b1);
                }
            }
#pragma unroll
            for (int nt = 0; nt < 4; nt++) {
                int col = nt * 8 + tg * 2;
                c[nt][0] = c[nt][0] * 0.125f + posw[(m0 + g) * 32 + col];
                c[nt][1] = c[nt][1] * 0.125f + posw[(m0 + g) * 32 + col + 1];
                c[nt][2] = c[nt][2] * 0.125f + posw[(m0 + g + 8) * 32 + col];
                c[nt][3] = c[nt][3] * 0.125f + posw[(m0 + g + 8) * 32 + col + 1];
            }
            float mx0 = -1e30f, mx1 = -1e30f;
#pragma unroll
            for (int nt = 0; nt < 4; nt++) {
                mx0 = fmaxf(mx0, fmaxf(c[nt][0], c[nt][1]));
                mx1 = fmaxf(mx1, fmaxf(c[nt][2], c[nt][3]));
            }
#pragma unroll
            for (int o = 1; o <= 2; o <<= 1) {
                mx0 = fmaxf(mx0, __shfl_xor_sync(0xffffffffu, mx0, o));
                mx1 = fmaxf(mx1, __shfl_xor_sync(0xffffffffu, mx1, o));
            }
            float sm0 = 0.f, sm1 = 0.f;
#pragma unroll
            for (int nt = 0; nt < 4; nt++) {
                c[nt][0] = __expf(c[nt][0] - mx0); sm0 += c[nt][0];
                c[nt][1] = __expf(c[nt][1] - mx0); sm0 += c[nt][1];
                c[nt][2] = __expf(c[nt][2] - mx1); sm1 += c[nt][2];
                c[nt][3] = __expf(c[nt][3] - mx1); sm1 += c[nt][3];
            }
#pragma unroll
            for (int o = 1; o <= 2; o <<= 1) {
                sm0 += __shfl_xor_sync(0xffffffffu, sm0, o);
                sm1 += __shfl_xor_sync(0xffffffffu, sm1, o);
            }
            float i0 = 1.f / sm0, i1 = 1.f / sm1;
#pragma unroll
            for (int nt = 0; nt < 4; nt++) {
                c[nt][0] *= i0; c[nt][1] *= i0; c[nt][2] *= i1; c[nt][3] *= i1;
            }
            uint32_t Ap[2][4];
#pragma unroll
            for (int kt2 = 0; kt2 < 2; kt2++) {
                Ap[kt2][0] = packbf(c[2 * kt2][0], c[2 * kt2][1]);
                Ap[kt2][1] = packbf(c[2 * kt2][2], c[2 * kt2][3]);
                Ap[kt2][2] = packbf(c[2 * kt2 + 1][0], c[2 * kt2 + 1][1]);
                Ap[kt2][3] = packbf(c[2 * kt2 + 1][2], c[2 * kt2 + 1][3]);
            }
#pragma unroll
            for (int nt = 0; nt < 8; nt++) {
                float o0 = 0.f, o1 = 0.f, o2 = 0.f, o3 = 0.f;
#pragma unroll
                for (int kt2 = 0; kt2 < 2; kt2++) {
                    uint32_t b0 = *(const uint32_t*)(vb + (nt * 8 + g) * 72 + kt2 * 16 + tg * 2);
                    uint32_t b1 = *(const uint32_t*)(vb + (nt * 8 + g) * 72 + kt2 * 16 + 8 + tg * 2);
                    MMA_BF16(o0, o1, o2, o3, Ap[kt2][0], Ap[kt2][1], Ap[kt2][2], Ap[kt2][3], b0, b1);
                }
                int colE = nt * 8 + tg * 2;
                so[(m0 + g) * 65 + colE]     = o0;
                so[(m0 + g) * 65 + colE + 1] = o1;
                so[(m0 + g + 8) * 65 + colE]     = o2;
                so[(m0 + g + 8) * 65 + colE + 1] = o3;
            }
        }
        __syncthreads();

        // ---- c1d 8->16 -> bf16 [16][264] ----
        {
            __nv_bfloat16* so16b = (__nv_bfloat16*)(smc + BY_SO16B);
            int d = tid >> 3, p2 = tid & 7;
            float vals[8];
#pragma unroll
            for (int c = 0; c < 8; c++) vals[c] = so[d * 65 + c * 8 + p2];
            const float* w = p.c1d_w + l * 128;
            const float* bb = p.c1d_b + l * 16;
#pragma unroll
            for (int o = 0; o < 16; o++) {
                float acc = bb[o];
#pragma unroll
                for (int c = 0; c < 8; c++) acc += w[o * 8 + c] * vals[c];
                so16b[o * 264 + tid] = __float2bfloat16(acc);
            }
        }
        __syncthreads();

        // ---- lin via mma: 4 k-chunks of 64, wtb [512][72] ----
        {
            const float* lw = p.lin_w + (size_t)l * 131072;
            __nv_bfloat16* wtb = (__nv_bfloat16*)(smc + BY_TB);
            const __nv_bfloat16* so16b = (const __nv_bfloat16*)(smc + BY_SO16B);
            float acc[8][4];
#pragma unroll
            for (int n = 0; n < 8; n++)
#pragma unroll
                for (int q = 0; q < 4; q++) acc[n][q] = 0.f;

            for (int ch = 0; ch < 4; ch++) {
                int d0 = ch * 64;
#pragma unroll 8
                for (int it = 0; it < 32; it++) {
                    int e4 = tid + NT * it;          // 0..8191
                    int o = e4 >> 4, k4 = (e4 & 15) * 4;
                    float4 v = *(const float4*)(lw + o * 256 + d0 + k4);
                    *(uint2*)(wtb + o * 72 + k4) =
                        make_uint2(packbf(v.x, v.y), packbf(v.z, v.w));
                }
                __syncthreads();
                uint32_t A[4][4];
#pragma unroll
                for (int ks = 0; ks < 4; ks++)
                    LDA4(A[ks], so16b, 264, 0, d0 + ks * 16, g, tg);
#pragma unroll
                for (int n = 0; n < 8; n++) {
                    int n0 = (wid * 8 + n) * 8;
#pragma unroll
                    for (int ks = 0; ks < 4; ks++) {
                        int k = ks * 16;
                        uint32_t b0 = *(const uint32_t*)(wtb + (n0 + g) * 72 + k + tg * 2);
                        uint32_t b1 = *(const uint32_t*)(wtb + (n0 + g) * 72 + k + 8 + tg * 2);
                        MMA_BF16(acc[n][0], acc[n][1], acc[n][2], acc[n][3],
                                 A[ks][0], A[ks][1], A[ks][2], A[ks][3], b0, b1);
                    }
                }
                __syncthreads();
            }
            const float* lb = p.lin_b + l * 512;
#pragma unroll
            for (int n = 0; n < 8; n++) {
                int o = (wid * 8 + n) * 8 + tg * 2;
                sx[g * 512 + o]           += acc[n][0] + lb[o];
                sx[g * 512 + o + 1]       += acc[n][1] + lb[o + 1];
                sx[(g + 8) * 512 + o]     += acc[n][2] + lb[o];
                sx[(g + 8) * 512 + o + 1] += acc[n][3] + lb[o + 1];
            }
        }
        __syncthreads();

        // ================= conv-FFN sublayer =================
        __nv_bfloat16* xpb  = (__nv_bfloat16*)(smc + BY_XP);
        __nv_bfloat16* f1wb = (__nv_bfloat16*)(smc + BY_F1W);
        __nv_bfloat16* t1   = (__nv_bfloat16*)(smc + BY_TA);
        __nv_bfloat16* t2   = (__nv_bfloat16*)(smc + BY_TB);
        __nv_bfloat16* fpwb = (__nv_bfloat16*)(smc + BY_FPWW);
        __nv_bfloat16* t3   = (__nv_bfloat16*)(smc + BY_TA);
        __nv_bfloat16* f2wb = (__nv_bfloat16*)(smc + BY_F2W);
        float* sb1  = (float*)(smc + BY_SB1);
        float* sbpw = (float*)(smc + BY_SBPW);
        float* sb2  = (float*)(smc + BY_SB2);
        float* sfdw = (float*)(smc + BY_FDW);

        {   // LN2 -> xp_bf [pos][40]
            const float* gg = p.ln2_g + l * DM; const float* bb = p.ln2_b + l * DM;
#pragma unroll
            for (int r = 0; r < 2; r++) {
                int h = wid + 8 * r;
                float s = 0.f, ss = 0.f;
#pragma unroll
                for (int i = 0; i < 16; i++) {
                    float v = sx[h * 512 + lane + 32 * i];
                    s += v; ss += v * v;
                }
                s = warp_sum(s); ss = warp_sum(ss);
                float mean = s * (1.f / 512.f);
                float rs = rsqrtf(ss * (1.f / 512.f) - mean * mean + EPSLN);
#pragma unroll
                for (int i = 0; i < 16; i++) {
                    int j = lane + 32 * i;
                    float v = (sx[h * 512 + j] - mean) * rs * gg[j] + bb[j];
                    int d = j >> 4, pp = h * 16 + (j & 15);
                    xpb[pp * 40 + d] = __float2bfloat16(v);
                }
            }
        }
        {   // stage f1w, f2w, biases, folded dw
            const float* w1 = p.f1_w + l * 4096;
#pragma unroll
            for (int it = 0; it < 4; it++) {
                int e4 = tid + NT * it;
                int n = e4 >> 3, k4 = (e4 & 7) * 4;
                float4 v = *(const float4*)(w1 + n * 32 + k4);
                *(uint2*)(f1wb + n * 40 + k4) =
                    make_uint2(packbf(v.x, v.y), packbf(v.z, v.w));
            }
            const float* w2 = p.f2_w + l * 4096;
#pragma unroll
            for (int it = 0; it < 4; it++) {
                int e4 = tid + NT * it;
                int i2 = e4 >> 5, o4 = (e4 & 31) * 4;
                float4 v = *(const float4*)(w2 + i2 * 128 + o4);
                *(uint2*)(f2wb + i2 * 136 + o4) =
                    make_uint2(packbf(v.x, v.y), packbf(v.z, v.w));
            }
            if (tid < 128) {
                sb1[tid]  = p.f1_b[l * 128 + tid];
                sbpw[tid] = p.fpw_b[l * 128 + tid];
                float* fw = sfdw + tid * 12;
                const float* dwp = p.fdw_w + l * 1152 + tid * 9;
#pragma unroll
                for (int k = 0; k < 9; k++) fw[k] = dwp[k];
                float sc = p.f_bng[l * 128 + tid] * rsqrtf(p.f_bnv[l * 128 + tid] + EPSLN);
                fw[9] = sc;
                fw[10] = (p.fdw_b[l * 128 + tid] - p.f_bnm[l * 128 + tid]) * sc
                         + p.f_bnb[l * 128 + tid];
            }
            if (tid < 32) sb2[tid] = p.f2_b[l * 32 + tid];
        }
        __syncthreads();

        // ---- f1: [256,128] = xp @ f1w^T, +bias, ReLU -> t1 ----
#pragma unroll
        for (int mi = 0; mi < 2; mi++) {
            int row = (wid * 2 + mi) * 16;
            uint32_t A[2][4];
#pragma unroll
            for (int ks = 0; ks < 2; ks++) LDA4(A[ks], xpb, 40, row, ks * 16, g, tg);
#pragma unroll
            for (int n = 0; n < 16; n++) {
                int n0 = n * 8;
                float bias0 = sb1[n0 + tg * 2], bias1 = sb1[n0 + tg * 2 + 1];
                float c0 = bias0, c1 = bias1, c2 = bias0, c3 = bias1;
#pragma unroll
                for (int ks = 0; ks < 2; ks++) {
                    int k = ks * 16;
                    uint32_t b0 = *(const uint32_t*)(f1wb + (n0 + g) * 40 + k + tg * 2);
                    uint32_t b1 = *(const uint32_t*)(f1wb + (n0 + g) * 40 + k + 8 + tg * 2);
                    MMA_BF16(c0, c1, c2, c3, A[ks][0], A[ks][1], A[ks][2], A[ks][3], b0, b1);
                }
                *(uint32_t*)(t1 + (row + g) * 136 + n0 + tg * 2) =
                    packbf(fmaxf(c0, 0.f), fmaxf(c1, 0.f));
                *(uint32_t*)(t1 + (row + g + 8) * 136 + n0 + tg * 2) =
                    packbf(fmaxf(c2, 0.f), fmaxf(c3, 0.f));
            }
        }
        __syncthreads();

        // ---- dw3x3 s1 + BN (rolling window, channel pairs) -> t2 ----
        {
            int cp = tid & 63, wq = tid >> 6;
            int w0 = wq * 4, c0 = cp * 2;
            const float* fwa = sfdw + c0 * 12;
            const float* fwb = sfdw + (c0 + 1) * 12;
            float2 kc[9];
#pragma unroll
            for (int t = 0; t < 9; t++) kc[t] = make_float2(fwa[t], fwb[t]);
            float2 scl = make_float2(fwa[9], fwb[9]);
            float2 shf = make_float2(fwa[10], fwb[10]);

            float2 rA[6], rB[6], rC[6];
#pragma unroll
            for (int i = 0; i < 6; i++) {
                rA[i] = make_float2(0.f, 0.f);
                int iw = w0 - 1 + i;
                rB[i] = ((unsigned)iw < 16u)
                    ? __bfloat1622float2(*(const __nv_bfloat162*)(t1 + iw * 136 + c0))
                    : make_float2(0.f, 0.f);
            }
#pragma unroll
            for (int h = 0; h < 16; h++) {
                if (h < 15) {
#pragma unroll
                    for (int i = 0; i < 6; i++) {
                        int iw = w0 - 1 + i;
                        rC[i] = ((unsigned)iw < 16u)
                            ? __bfloat1622float2(*(const __nv_bfloat162*)(t1 + ((h + 1) * 16 + iw) * 136 + c0))
                            : make_float2(0.f, 0.f);
                    }
                } else {
#pragma unroll
                    for (int i = 0; i < 6; i++) rC[i] = make_float2(0.f, 0.f);
                }
#pragma unroll
                for (int j = 0; j < 4; j++) {
                    float ax = rA[j].x * kc[0].x + rA[j+1].x * kc[1].x + rA[j+2].x * kc[2].x
                             + rB[j].x * kc[3].x + rB[j+1].x * kc[4].x + rB[j+2].x * kc[5].x
                             + rC[j].x * kc[6].x + rC[j+1].x * kc[7].x + rC[j+2].x * kc[8].x;
                    float ay = rA[j].y * kc[0].y + rA[j+1].y * kc[1].y + rA[j+2].y * kc[2].y
                             + rB[j].y * kc[3].y + rB[j+1].y * kc[4].y + rB[j+2].y * kc[5].y
                             + rC[j].y * kc[6].y + rC[j+1].y * kc[7].y + rC[j+2].y * kc[8].y;
                    *(uint32_t*)(t2 + (h * 16 + w0 + j) * 136 + c0) =
                        packbf(ax * scl.x + shf.x, ay * scl.y + shf.y);
                }
#pragma unroll
                for (int i = 0; i < 6; i++) { rA[i] = rB[i]; rB[i] = rC[i]; }
            }
            // stage fpw weights (overlays dead xp/f1w)
            const float* wpw = p.fpw_w + (size_t)l * 16384;
#pragma unroll
            for (int it = 0; it < 16; it++) {
                int e4 = tid + NT * it;
                int o = e4 >> 5, c4 = (e4 & 31) * 4;
                float4 v = *(const float4*)(wpw + o * 128 + c4);
                *(uint2*)(fpwb + o * 136 + c4) =
                    make_uint2(packbf(v.x, v.y), packbf(v.z, v.w));
            }
        }
        __syncthreads();

        // ---- fpw: [256,128] = t2 @ fpw^T, +bias, ReLU -> t3 ----
#pragma unroll
        for (int mi = 0; mi < 2; mi++) {
            int row = (wid * 2 + mi) * 16;
            uint32_t A[8][4];
#pragma unroll
            for (int ks = 0; ks < 8; ks++) LDA4(A[ks], t2, 136, row, ks * 16, g, tg);
#pragma unroll
            for (int n = 0; n < 16; n++) {
                int n0 = n * 8;
                float bias0 = sbpw[n0 + tg * 2], bias1 = sbpw[n0 + tg * 2 + 1];
                float c0 = bias0, c1 = bias1, c2 = bias0, c3 = bias1;
#pragma unroll
                for (int ks = 0; ks < 8; ks++) {
                    int k = ks * 16;
                    uint32_t b0 = *(const uint32_t*)(fpwb + (n0 + g) * 136 + k + tg * 2);
                    uint32_t b1 = *(const uint32_t*)(fpwb + (n0 + g) * 136 + k + 8 + tg * 2);
                    MMA_BF16(c0, c1, c2, c3, A[ks][0], A[ks][1], A[ks][2], A[ks][3], b0, b1);
                }
                *(uint32_t*)(t3 + (row + g) * 136 + n0 + tg * 2) =
                    packbf(fmaxf(c0, 0.f), fmaxf(c1, 0.f));
                *(uint32_t*)(t3 + (row + g + 8) * 136 + n0 + tg * 2) =
                    packbf(fmaxf(c2, 0.f), fmaxf(c3, 0.f));
            }
        }
        __syncthreads();

        // ---- f2: [256,32] = t3 @ f2w^T, +bias, residual -> sx ----
#pragma unroll
        for (int mi = 0; mi < 2; mi++) {
            int row = (wid * 2 + mi) * 16;
            uint32_t A[8][4];
#pragma unroll
            for (int ks = 0; ks < 8; ks++) LDA4(A[ks], t3, 136, row, ks * 16, g, tg);
#pragma unroll
            for (int n = 0; n < 4; n++) {
                int n0 = n * 8;
                float c0 = 0.f, c1 = 0.f, c2 = 0.f, c3 = 0.f;
#pragma unroll
                for (int ks = 0; ks < 8; ks++) {
                    int k = ks * 16;
                    uint32_t b0 = *(const uint32_t*)(f2wb + (n0 + g) * 136 + k + tg * 2);
                    uint32_t b1 = *(const uint32_t*)(f2wb + (n0 + g) * 136 + k + 8 + tg * 2);
                    MMA_BF16(c0, c1, c2, c3, A[ks][0], A[ks][1], A[ks][2], A[ks][3], b0, b1);
                }
                int i = n0 + tg * 2;
                int pos = row + g, h = pos >> 4, w = pos & 15;
                sx[h * 512 + i * 16 + w]       += c0 + sb2[i];
                sx[h * 512 + (i + 1) * 16 + w] += c1 + sb2[i + 1];
                pos = row + g + 8; h = pos >> 4; w = pos & 15;
                sx[h * 512 + i * 16 + w]       += c2 + sb2[i];
                sx[h * 512 + (i + 1) * 16 + w] += c3 + sb2[i + 1];
            }
        }
        __syncthreads();
    } // layers

    // ---- write out ----
    {
        float4* og = (float4*)(p.out + (size_t)b * 8192);
        const float4* sx4 = (const float4*)sx;
#pragma unroll
        for (int it = 0; it < 8; it++) og[tid + NT * it] = sx4[tid + NT * it];
    }
}

extern "C" void kernel_launch(void* const* d_in, const int* in_sizes, int n_in,
                              void* d_out, int out_size) {
    Params p;
    p.x        = (const float*)d_in[0];
    p.ln1_g    = (const float*)d_in[1];
    p.ln1_b    = (const float*)d_in[2];
    p.ln2_g    = (const float*)d_in[3];
    p.ln2_b    = (const float*)d_in[4];
    p.qkv_dw   = (const float*)d_in[5];
    p.qkv_bng  = (const float*)d_in[6];
    p.qkv_bnb  = (const float*)d_in[7];
    p.qkv_bnm  = (const float*)d_in[8];
    p.qkv_bnv  = (const float*)d_in[9];
    p.qkv_pw   = (const float*)d_in[10];
    p.position = (const float*)d_in[11];
    p.c1d_w    = (const float*)d_in[12];
    p.c1d_b    = (const float*)d_in[13];
    p.lin_w    = (const float*)d_in[14];
    p.lin_b    = (const float*)d_in[15];
    p.f1_w     = (const float*)d_in[16];
    p.f1_b     = (const float*)d_in[17];
    p.fdw_w    = (const float*)d_in[18];
    p.fdw_b    = (const float*)d_in[19];
    p.f_bng    = (const float*)d_in[20];
    p.f_bnb    = (const float*)d_in[21];
    p.f_bnm    = (const float*)d_in[22];
    p.f_bnv    = (const float*)d_in[23];
    p.fpw_w    = (const float*)d_in[24];
    p.fpw_b    = (const float*)d_in[25];
    p.f2_w     = (const float*)d_in[26];
    p.f2_b     = (const float*)d_in[27];
    p.out      = (float*)d_out;

    int nb = in_sizes[0] / (16 * 512);   // 2048

    cudaFuncSetAttribute(encoder_kernel,
                         cudaFuncAttributeMaxDynamicSharedMemorySize, SMEM_BYTES);
    encoder_kernel<<<nb, NT, SMEM_BYTES>>>(p);
}